// round 9
// baseline (speedup 1.0000x reference)
#include <cuda_runtime.h>
#include <cuda_bf16.h>
#include <cstdint>

// ---------------- problem constants ----------------
#define D_DIM   1024
#define E_DIM   4
#define R_DIM   64
#define ER_DIM  256
#define B_ROWS  32768
#define N_LAYERS 3

#define BM      64            // rows per block
#define NTHR    256           // 8 warps
#define NBLK    (B_ROWS / BM) // 512

// smem strides (floats) — chosen so mma B-fragment LDS is bank-conflict-free
#define BSTR 264              // 256 + 8 pad   (GEMM1/2 B tiles, vS/wS)
#define CSTR 136              // 128 + 8 pad   (GEMM3 B tiles, output stage)
#define XSTR 36               // 32 + 4 pad    (x chunk)

// smem layout (float offsets)
#define OFF_BS   0            // [2][32][264] = 16896  (also GEMM3 [2][32][136], also stage [64][136])
#define OFF_VS   16896        // [64][264]    = 16896  (v1 -> then w)
#define OFF_XS   33792        // [2][64][36]  = 4608   (aliased by gpart [8][64][8]=4096 after GEMM1)
#define OFF_GWS  38400        // [2][32][8]   = 512
#define OFF_GATE 38912        // [64][4]      = 256
#define SMEM_FLOATS 39168
#define SMEM_BYTES  (SMEM_FLOATS * 4)

// ---------------- device scratch (prepped weights) ----------------
__device__ float g_Vt[N_LAYERS * D_DIM * ER_DIM];    // [l][d][e*64+r]
__device__ float g_Ut[N_LAYERS * ER_DIM * D_DIM];    // [l][e*64+r][d]
__device__ float g_Cb[N_LAYERS * ER_DIM * ER_DIM];   // [l][e*64+s][e*64+r] block-diag
__device__ float g_gwT[D_DIM * 8];                   // [d][e] (e>=4 zero)

// ---------------- small helpers ----------------
__device__ __forceinline__ float rna_tf32(float x) {
    uint32_t u; asm("cvt.rna.tf32.f32 %0, %1;" : "=r"(u) : "f"(x));
    return __uint_as_float(u);
}
__device__ __forceinline__ uint32_t fu(float x) { return __float_as_uint(x); }

__device__ __forceinline__ void mma_tf32(float* d,
                                         uint32_t a0, uint32_t a1, uint32_t a2, uint32_t a3,
                                         uint32_t b0, uint32_t b1) {
    asm volatile(
        "mma.sync.aligned.m16n8k8.row.col.f32.tf32.tf32.f32 "
        "{%0,%1,%2,%3}, {%4,%5,%6,%7}, {%8,%9}, {%0,%1,%2,%3};\n"
        : "+f"(d[0]), "+f"(d[1]), "+f"(d[2]), "+f"(d[3])
        : "r"(a0), "r"(a1), "r"(a2), "r"(a3), "r"(b0), "r"(b1));
}

__device__ __forceinline__ void cp16(float* smem_dst, const float* gsrc) {
    uint32_t s = (uint32_t)__cvta_generic_to_shared(smem_dst);
    asm volatile("cp.async.cg.shared.global [%0], [%1], 16;\n" :: "r"(s), "l"(gsrc));
}
#define CP_COMMIT() asm volatile("cp.async.commit_group;\n" ::: "memory")
#define CP_WAIT1()  asm volatile("cp.async.wait_group 1;\n" ::: "memory")
#define CP_WAIT0()  asm volatile("cp.async.wait_group 0;\n" ::: "memory")

// ---------------- weight prep: tf32 round + transpose ----------------
__global__ void prep_k(const float* __restrict__ U, const float* __restrict__ V,
                       const float* __restrict__ C, const float* __restrict__ gw) {
    const int stride = gridDim.x * blockDim.x;
    const int tid0 = blockIdx.x * blockDim.x + threadIdx.x;

    // Vt and Ut (both N_LAYERS*D*ER = 786432 elements)
    for (int i = tid0; i < N_LAYERS * D_DIM * ER_DIM; i += stride) {
        const int l = i / (D_DIM * ER_DIM);
        const int rem = i % (D_DIM * ER_DIM);
        {   // Vt[l][d][e*64+r] = V[l,e,d,r]
            const int d = rem >> 8, n = rem & 255, e = n >> 6, r = n & 63;
            g_Vt[i] = rna_tf32(V[(((l * E_DIM + e) * D_DIM + d) * R_DIM) + r]);
        }
        {   // Ut[l][e*64+r][d] = U[l,e,d,r]
            const int er = rem >> 10, d = rem & 1023, e = er >> 6, r = er & 63;
            g_Ut[i] = rna_tf32(U[(((l * E_DIM + e) * D_DIM + d) * R_DIM) + r]);
        }
    }
    // Cb[l][e*64+s][e'*64+r] = C[l,e,r,s] if e==e' else 0
    for (int i = tid0; i < N_LAYERS * ER_DIM * ER_DIM; i += stride) {
        const int l = i / (ER_DIM * ER_DIM);
        const int rem = i % (ER_DIM * ER_DIM);
        const int sg = rem >> 8, rg = rem & 255;
        const int es = sg >> 6, er_ = rg >> 6;
        g_Cb[i] = (es == er_)
            ? rna_tf32(C[(((l * E_DIM + es) * R_DIM + (rg & 63)) * R_DIM) + (sg & 63)])
            : 0.0f;
    }
    // gwT[d][e]
    for (int i = tid0; i < D_DIM * 8; i += stride) {
        const int d = i >> 3, e = i & 7;
        g_gwT[i] = (e < E_DIM) ? rna_tf32(gw[e * D_DIM + d]) : 0.0f;
    }
}

// ---------------- fused layer kernel ----------------
__global__ void __launch_bounds__(NTHR, 1)
layer_k(const float* __restrict__ xin, float* __restrict__ xout,
        const float* __restrict__ x0g, const float* __restrict__ bias_all,
        int l, int x0_is_xin) {
    extern __shared__ float sm[];
    float* Bs    = sm + OFF_BS;
    float* vS    = sm + OFF_VS;
    float* xs    = sm + OFF_XS;
    float* gpart = sm + OFF_XS;   // alias (xs dead when used)
    float* gws   = sm + OFF_GWS;
    float* gateS = sm + OFF_GATE;

    const int tid  = threadIdx.x;
    const int warp = tid >> 5, lane = tid & 31;
    const int g = lane >> 2, t = lane & 3;
    const int mw = warp >> 1, nw = warp & 1;
    const int mbase = mw * 16;
    const int nbase = nw * 128;   // GEMM1/2 warp col base
    const int nbase2 = nw * 64;   // GEMM3 warp col base
    const int brow = blockIdx.x * BM;

    const float* Vt = g_Vt + l * (D_DIM * ER_DIM);
    const float* Ut = g_Ut + l * (ER_DIM * D_DIM);
    const float* Cb = g_Cb + l * (ER_DIM * ER_DIM);
    const float* bl = bias_all + l * D_DIM;

    float acc[64];
    float gacc[16];
    #pragma unroll
    for (int i = 0; i < 64; i++) acc[i] = 0.0f;
    #pragma unroll
    for (int i = 0; i < 16; i++) gacc[i] = 0.0f;

    // ============ Phase A: v1_pre = x @ Vt  (M=64, N=256, K=1024) + gating ============
    // prologue: load chunk 0
    {
        const int k0 = 0;
        #pragma unroll
        for (int j = 0; j < 2; j++) {
            int i = tid + j * 256;
            int r = i >> 3, c4 = i & 7;
            cp16(xs + r * XSTR + c4 * 4, xin + (size_t)(brow + r) * D_DIM + k0 + c4 * 4);
        }
        #pragma unroll
        for (int j = 0; j < 8; j++) {
            int i = tid + j * 256;
            int r = i >> 6, c4 = i & 63;
            cp16(Bs + r * BSTR + c4 * 4, Vt + (k0 + r) * ER_DIM + c4 * 4);
        }
        if (tid < 64) {
            int r = tid >> 1, c4 = tid & 1;
            cp16(gws + r * 8 + c4 * 4, g_gwT + (k0 + r) * 8 + c4 * 4);
        }
        CP_COMMIT();
    }

    for (int c = 0; c < 32; c++) {
        const int buf = c & 1;
        if (c + 1 < 32) {
            const int k0 = (c + 1) * 32;
            const int nb = buf ^ 1;
            #pragma unroll
            for (int j = 0; j < 2; j++) {
                int i = tid + j * 256;
                int r = i >> 3, c4 = i & 7;
                cp16(xs + nb * 2304 + r * XSTR + c4 * 4, xin + (size_t)(brow + r) * D_DIM + k0 + c4 * 4);
            }
            #pragma unroll
            for (int j = 0; j < 8; j++) {
                int i = tid + j * 256;
                int r = i >> 6, c4 = i & 63;
                cp16(Bs + nb * 8448 + r * BSTR + c4 * 4, Vt + (k0 + r) * ER_DIM + c4 * 4);
            }
            if (tid < 64) {
                int r = tid >> 1, c4 = tid & 1;
                cp16(gws + nb * 256 + r * 8 + c4 * 4, g_gwT + (k0 + r) * 8 + c4 * 4);
            }
            CP_COMMIT();
            CP_WAIT1();
        } else {
            CP_WAIT0();
        }
        __syncthreads();

        const float* xb = xs + buf * 2304;
        const float* bb = Bs + buf * 8448;
        const bool dogate = ((c & 7) == warp);
        #pragma unroll
        for (int kk = 0; kk < 4; kk++) {
            const int kb = kk * 8;
            uint32_t a0 = fu(rna_tf32(xb[(mbase + g) * XSTR + kb + t]));
            uint32_t a1 = fu(rna_tf32(xb[(mbase + g + 8) * XSTR + kb + t]));
            uint32_t a2 = fu(rna_tf32(xb[(mbase + g) * XSTR + kb + t + 4]));
            uint32_t a3 = fu(rna_tf32(xb[(mbase + g + 8) * XSTR + kb + t + 4]));
            #pragma unroll
            for (int nt = 0; nt < 16; nt++) {
                uint32_t b0 = fu(bb[(kb + t) * BSTR + nbase + nt * 8 + g]);
                uint32_t b1 = fu(bb[(kb + t + 4) * BSTR + nbase + nt * 8 + g]);
                mma_tf32(acc + nt * 4, a0, a1, a2, a3, b0, b1);
            }
            if (dogate) {
                const float* gb = gws + buf * 256;
                uint32_t gb0 = fu(gb[(kb + t) * 8 + g]);
                uint32_t gb1 = fu(gb[(kb + t + 4) * 8 + g]);
                #pragma unroll
                for (int mt = 0; mt < 4; mt++) {
                    uint32_t c0 = fu(rna_tf32(xb[(mt * 16 + g) * XSTR + kb + t]));
                    uint32_t c1 = fu(rna_tf32(xb[(mt * 16 + g + 8) * XSTR + kb + t]));
                    uint32_t c2 = fu(rna_tf32(xb[(mt * 16 + g) * XSTR + kb + t + 4]));
                    uint32_t c3 = fu(rna_tf32(xb[(mt * 16 + g + 8) * XSTR + kb + t + 4]));
                    mma_tf32(gacc + mt * 4, c0, c1, c2, c3, gb0, gb1);
                }
            }
        }
        __syncthreads();
    }

    // v1 = tanh(acc) -> vS (tf32-rounded);  gating partials -> gpart
    #pragma unroll
    for (int nt = 0; nt < 16; nt++) {
        const int col = nbase + nt * 8 + 2 * t;
        vS[(mbase + g) * BSTR + col]         = rna_tf32(tanhf(acc[nt * 4 + 0]));
        vS[(mbase + g) * BSTR + col + 1]     = rna_tf32(tanhf(acc[nt * 4 + 1]));
        vS[(mbase + g + 8) * BSTR + col]     = rna_tf32(tanhf(acc[nt * 4 + 2]));
        vS[(mbase + g + 8) * BSTR + col + 1] = rna_tf32(tanhf(acc[nt * 4 + 3]));
    }
    #pragma unroll
    for (int mt = 0; mt < 4; mt++) {
        const int row = mt * 16 + g;
        const int cc = 2 * t;
        gpart[warp * 512 + row * 8 + cc]           = gacc[mt * 4 + 0];
        gpart[warp * 512 + row * 8 + cc + 1]       = gacc[mt * 4 + 1];
        gpart[warp * 512 + (row + 8) * 8 + cc]     = gacc[mt * 4 + 2];
        gpart[warp * 512 + (row + 8) * 8 + cc + 1] = gacc[mt * 4 + 3];
    }
    __syncthreads();

    // softmax over experts (tid -> row = tid>>2, e = tid&3; groups of 4 lanes)
    {
        const int row = tid >> 2, e = tid & 3;
        float s = 0.0f;
        #pragma unroll
        for (int w = 0; w < 8; w++) s += gpart[w * 512 + row * 8 + e];
        float m = s;
        m = fmaxf(m, __shfl_xor_sync(0xffffffffu, m, 1));
        m = fmaxf(m, __shfl_xor_sync(0xffffffffu, m, 2));
        float p = __expf(s - m);
        float su = p;
        su += __shfl_xor_sync(0xffffffffu, su, 1);
        su += __shfl_xor_sync(0xffffffffu, su, 2);
        gateS[tid] = p / su;
    }
    __syncthreads();

    // ============ Phase B: v2_pre = v1 @ Cb  (M=64, N=256, K=256) ============
    #pragma unroll
    for (int i = 0; i < 64; i++) acc[i] = 0.0f;

    {   // prologue
        #pragma unroll
        for (int j = 0; j < 8; j++) {
            int i = tid + j * 256;
            int r = i >> 6, c4 = i & 63;
            cp16(Bs + r * BSTR + c4 * 4, Cb + r * ER_DIM + c4 * 4);
        }
        CP_COMMIT();
    }
    for (int c = 0; c < 8; c++) {
        const int buf = c & 1;
        if (c + 1 < 8) {
            const int k0 = (c + 1) * 32;
            const int nb = buf ^ 1;
            #pragma unroll
            for (int j = 0; j < 8; j++) {
                int i = tid + j * 256;
                int r = i >> 6, c4 = i & 63;
                cp16(Bs + nb * 8448 + r * BSTR + c4 * 4, Cb + (k0 + r) * ER_DIM + c4 * 4);
            }
            CP_COMMIT();
            CP_WAIT1();
        } else {
            CP_WAIT0();
        }
        __syncthreads();

        const float* bb = Bs + buf * 8448;
        #pragma unroll
        for (int kk = 0; kk < 4; kk++) {
            const int kg = c * 32 + kk * 8;
            const int kb = kk * 8;
            uint32_t a0 = fu(vS[(mbase + g) * BSTR + kg + t]);
            uint32_t a1 = fu(vS[(mbase + g + 8) * BSTR + kg + t]);
            uint32_t a2 = fu(vS[(mbase + g) * BSTR + kg + t + 4]);
            uint32_t a3 = fu(vS[(mbase + g + 8) * BSTR + kg + t + 4]);
            #pragma unroll
            for (int nt = 0; nt < 16; nt++) {
                uint32_t b0 = fu(bb[(kb + t) * BSTR + nbase + nt * 8 + g]);
                uint32_t b1 = fu(bb[(kb + t + 4) * BSTR + nbase + nt * 8 + g]);
                mma_tf32(acc + nt * 4, a0, a1, a2, a3, b0, b1);
            }
        }
        __syncthreads();
    }

    // w = gate * tanh(v2_pre) -> overwrite vS (as wS), tf32-rounded
    #pragma unroll
    for (int nt = 0; nt < 16; nt++) {
        const int col = nbase + nt * 8 + 2 * t;   // even; col and col+1 share expert block
        const int e = col >> 6;
        const float g0 = gateS[(mbase + g) * 4 + e];
        const float g1 = gateS[(mbase + g + 8) * 4 + e];
        vS[(mbase + g) * BSTR + col]         = rna_tf32(g0 * tanhf(acc[nt * 4 + 0]));
        vS[(mbase + g) * BSTR + col + 1]     = rna_tf32(g0 * tanhf(acc[nt * 4 + 1]));
        vS[(mbase + g + 8) * BSTR + col]     = rna_tf32(g1 * tanhf(acc[nt * 4 + 2]));
        vS[(mbase + g + 8) * BSTR + col + 1] = rna_tf32(g1 * tanhf(acc[nt * 4 + 3]));
    }
    __syncthreads();

    // ============ Phase C: out = w @ Ut (M=64, N=1024 in 8 chunks of 128, K=256) + epilogue ============
    for (int nc = 0; nc < 8; nc++) {
        const int n0 = nc * 128;
        float acc3[32];
        #pragma unroll
        for (int i = 0; i < 32; i++) acc3[i] = 0.0f;

        {   // prologue
            #pragma unroll
            for (int j = 0; j < 4; j++) {
                int i = tid + j * 256;
                int r = i >> 5, c4 = i & 31;
                cp16(Bs + r * CSTR + c4 * 4, Ut + r * D_DIM + n0 + c4 * 4);
            }
            CP_COMMIT();
        }
        for (int c = 0; c < 8; c++) {
            const int buf = c & 1;
            if (c + 1 < 8) {
                const int k0 = (c + 1) * 32;
                const int nb = buf ^ 1;
                #pragma unroll
                for (int j = 0; j < 4; j++) {
                    int i = tid + j * 256;
                    int r = i >> 5, c4 = i & 31;
                    cp16(Bs + nb * 4352 + r * CSTR + c4 * 4, Ut + (k0 + r) * D_DIM + n0 + c4 * 4);
                }
                CP_COMMIT();
                CP_WAIT1();
            } else {
                CP_WAIT0();
            }
            __syncthreads();

            const float* bb = Bs + buf * 4352;
            #pragma unroll
            for (int kk = 0; kk < 4; kk++) {
                const int kg = c * 32 + kk * 8;
                const int kb = kk * 8;
                uint32_t a0 = fu(vS[(mbase + g) * BSTR + kg + t]);
                uint32_t a1 = fu(vS[(mbase + g + 8) * BSTR + kg + t]);
                uint32_t a2 = fu(vS[(mbase + g) * BSTR + kg + t + 4]);
                uint32_t a3 = fu(vS[(mbase + g + 8) * BSTR + kg + t + 4]);
                #pragma unroll
                for (int nt = 0; nt < 8; nt++) {
                    uint32_t b0 = fu(bb[(kb + t) * CSTR + nbase2 + nt * 8 + g]);
                    uint32_t b1 = fu(bb[(kb + t + 4) * CSTR + nbase2 + nt * 8 + g]);
                    mma_tf32(acc3 + nt * 4, a0, a1, a2, a3, b0, b1);
                }
            }
            __syncthreads();
        }

        // stage acc3 -> smem (Bs region) for coalesced epilogue
        float* stg = Bs;
        #pragma unroll
        for (int nt = 0; nt < 8; nt++) {
            const int col = nbase2 + nt * 8 + 2 * t;
            stg[(mbase + g) * CSTR + col]         = acc3[nt * 4 + 0];
            stg[(mbase + g) * CSTR + col + 1]     = acc3[nt * 4 + 1];
            stg[(mbase + g + 8) * CSTR + col]     = acc3[nt * 4 + 2];
            stg[(mbase + g + 8) * CSTR + col + 1] = acc3[nt * 4 + 3];
        }
        __syncthreads();

        // epilogue: out = x_l + x0 * (moe + bias)   (fully coalesced float4)
        #pragma unroll
        for (int j = 0; j < 8; j++) {
            int i = tid + j * 256;
            int r = i >> 5, c4 = i & 31;
            const int gr = brow + r;
            const int gc = n0 + c4 * 4;
            float4 s  = *reinterpret_cast<const float4*>(stg + r * CSTR + c4 * 4);
            float4 xv = *reinterpret_cast<const float4*>(xin + (size_t)gr * D_DIM + gc);
            float4 x0v = x0_is_xin ? xv
                       : *reinterpret_cast<const float4*>(x0g + (size_t)gr * D_DIM + gc);
            float4 bv = *reinterpret_cast<const float4*>(bl + gc);
            float4 o;
            o.x = xv.x + x0v.x * (s.x + bv.x);
            o.y = xv.y + x0v.y * (s.y + bv.y);
            o.z = xv.z + x0v.z * (s.z + bv.z);
            o.w = xv.w + x0v.w * (s.w + bv.w);
            *reinterpret_cast<float4*>(xout + (size_t)gr * D_DIM + gc) = o;
        }
        __syncthreads();
    }
}

// ---------------- launch ----------------
extern "C" void kernel_launch(void* const* d_in, const int* in_sizes, int n_in,
                              void* d_out, int out_size) {
    const float* inputs = (const float*)d_in[0];
    const float* U      = (const float*)d_in[1];
    const float* V      = (const float*)d_in[2];
    const float* C      = (const float*)d_in[3];
    const float* gw     = (const float*)d_in[4];
    const float* bias   = (const float*)d_in[5];
    float* out = (float*)d_out;
    (void)in_sizes; (void)n_in; (void)out_size;

    cudaFuncSetAttribute(layer_k, cudaFuncAttributeMaxDynamicSharedMemorySize, SMEM_BYTES);

    prep_k<<<1024, 256>>>(U, V, C, gw);
    layer_k<<<NBLK, NTHR, SMEM_BYTES>>>(inputs, out, inputs, bias, 0, 1);
    layer_k<<<NBLK, NTHR, SMEM_BYTES>>>(out,    out, inputs, bias, 1, 0);
    layer_k<<<NBLK, NTHR, SMEM_BYTES>>>(out,    out, inputs, bias, 2, 0);
}

// round 10
// speedup vs baseline: 1.3972x; 1.3972x over previous
#include <cuda_runtime.h>
#include <cuda_bf16.h>
#include <cstdint>

// ---------------- problem constants ----------------
#define D_DIM   1024
#define E_DIM   4
#define R_DIM   64
#define ER_DIM  256
#define B_ROWS  32768
#define N_LAYERS 3

#define BM      32            // rows per block
#define NTHR    256           // 8 warps
#define NBLK    (B_ROWS / BM) // 1024

// smem strides (floats) — bank-conflict-free for the mma fragment patterns
#define BSTR 264              // 256 + 8  (B tiles; 264%32==8 -> b-frag LDS hits all 32 banks)
#define VSTR 260              // 256 + 4  (vS/wS A operand; 260%32==4 -> a-frag LDS conflict-free)
#define XSTR 36               // 32 + 4   (x chunk; 36%32==4 -> a-frag LDS conflict-free)

// smem layout (float offsets)
#define OFF_BS   0            // [2][32][264] = 16896  (also GEMM3 stage [32][264])
#define OFF_VS   16896        // [32][260]    = 8320   (v1 -> then w)
#define OFF_XS   25216        // [2][32][36]  = 2304   (aliased by gpart [8][32][8]=2048)
#define OFF_GWS  27520        // [2][32][8]   = 512
#define OFF_GATE 28032        // [32][4]      = 128
#define SMEM_FLOATS 28160
#define SMEM_BYTES  (SMEM_FLOATS * 4)   // 112640 B -> 2 CTAs/SM

// ---------------- device scratch (prepped weights) ----------------
__device__ float g_Vt[N_LAYERS * D_DIM * ER_DIM];    // [l][d][e*64+r]
__device__ float g_Ut[N_LAYERS * ER_DIM * D_DIM];    // [l][e*64+r][d]
__device__ float g_Cb[N_LAYERS * ER_DIM * ER_DIM];   // [l][e*64+s][e*64+r] block-diag
__device__ float g_gwT[D_DIM * 8];                   // [d][e] (e>=4 zero)

// ---------------- small helpers ----------------
__device__ __forceinline__ float rna_tf32(float x) {
    uint32_t u; asm("cvt.rna.tf32.f32 %0, %1;" : "=r"(u) : "f"(x));
    return __uint_as_float(u);
}
__device__ __forceinline__ uint32_t fu(float x) { return __float_as_uint(x); }

__device__ __forceinline__ void mma_tf32(float* d,
                                         uint32_t a0, uint32_t a1, uint32_t a2, uint32_t a3,
                                         uint32_t b0, uint32_t b1) {
    asm volatile(
        "mma.sync.aligned.m16n8k8.row.col.f32.tf32.tf32.f32 "
        "{%0,%1,%2,%3}, {%4,%5,%6,%7}, {%8,%9}, {%0,%1,%2,%3};\n"
        : "+f"(d[0]), "+f"(d[1]), "+f"(d[2]), "+f"(d[3])
        : "r"(a0), "r"(a1), "r"(a2), "r"(a3), "r"(b0), "r"(b1));
}

__device__ __forceinline__ void cp16(float* smem_dst, const float* gsrc) {
    uint32_t s = (uint32_t)__cvta_generic_to_shared(smem_dst);
    asm volatile("cp.async.cg.shared.global [%0], [%1], 16;\n" :: "r"(s), "l"(gsrc));
}
#define CP_COMMIT() asm volatile("cp.async.commit_group;\n" ::: "memory")
#define CP_WAIT1()  asm volatile("cp.async.wait_group 1;\n" ::: "memory")
#define CP_WAIT0()  asm volatile("cp.async.wait_group 0;\n" ::: "memory")

// ---------------- weight prep: tf32 round + transpose ----------------
__global__ void prep_k(const float* __restrict__ U, const float* __restrict__ V,
                       const float* __restrict__ C, const float* __restrict__ gw) {
    const int stride = gridDim.x * blockDim.x;
    const int tid0 = blockIdx.x * blockDim.x + threadIdx.x;

    for (int i = tid0; i < N_LAYERS * D_DIM * ER_DIM; i += stride) {
        const int l = i / (D_DIM * ER_DIM);
        const int rem = i % (D_DIM * ER_DIM);
        {   // Vt[l][d][e*64+r] = V[l,e,d,r]
            const int d = rem >> 8, n = rem & 255, e = n >> 6, r = n & 63;
            g_Vt[i] = rna_tf32(V[(((l * E_DIM + e) * D_DIM + d) * R_DIM) + r]);
        }
        {   // Ut[l][e*64+r][d] = U[l,e,d,r]
            const int er = rem >> 10, d = rem & 1023, e = er >> 6, r = er & 63;
            g_Ut[i] = rna_tf32(U[(((l * E_DIM + e) * D_DIM + d) * R_DIM) + r]);
        }
    }
    // Cb[l][e*64+s][e'*64+r] = C[l,e,r,s] if e==e' else 0
    for (int i = tid0; i < N_LAYERS * ER_DIM * ER_DIM; i += stride) {
        const int l = i / (ER_DIM * ER_DIM);
        const int rem = i % (ER_DIM * ER_DIM);
        const int sg = rem >> 8, rg = rem & 255;
        const int es = sg >> 6, er_ = rg >> 6;
        g_Cb[i] = (es == er_)
            ? rna_tf32(C[(((l * E_DIM + es) * R_DIM + (rg & 63)) * R_DIM) + (sg & 63)])
            : 0.0f;
    }
    // gwT[d][e]
    for (int i = tid0; i < D_DIM * 8; i += stride) {
        const int d = i >> 3, e = i & 7;
        g_gwT[i] = (e < E_DIM) ? rna_tf32(gw[e * D_DIM + d]) : 0.0f;
    }
}

// ---------------- fused layer kernel ----------------
__global__ void __launch_bounds__(NTHR, 2)
layer_k(const float* __restrict__ xin, float* __restrict__ xout,
        const float* __restrict__ x0g, const float* __restrict__ bias_all,
        int l, int x0_is_xin) {
    extern __shared__ float sm[];
    float* Bs    = sm + OFF_BS;
    float* vS    = sm + OFF_VS;
    float* xs    = sm + OFF_XS;
    float* gpart = sm + OFF_XS;   // alias (xs dead when used)
    float* gws   = sm + OFF_GWS;
    float* gateS = sm + OFF_GATE;

    const int tid  = threadIdx.x;
    const int warp = tid >> 5, lane = tid & 31;
    const int g = lane >> 2, t = lane & 3;
    const int nbase = warp * 32;         // warp's 32-column slice (all GEMMs)
    const int brow = blockIdx.x * BM;

    const float* Vt = g_Vt + l * (D_DIM * ER_DIM);
    const float* Ut = g_Ut + l * (ER_DIM * D_DIM);
    const float* Cb = g_Cb + l * (ER_DIM * ER_DIM);
    const float* bl = bias_all + l * D_DIM;

    float acc[32];                       // 2 m-tiles x 4 n-tiles x 4
    float gacc[8];                       // gating: 2 m-tiles x 4
    #pragma unroll
    for (int i = 0; i < 32; i++) acc[i] = 0.0f;
    #pragma unroll
    for (int i = 0; i < 8; i++) gacc[i] = 0.0f;

    // ============ Phase A: v1_pre = x @ Vt  (M=32, N=256, K=1024) + gating ============
    {   // prologue: chunk 0
        {
            int r = tid >> 3, c4 = tid & 7;
            cp16(xs + r * XSTR + c4 * 4, xin + (size_t)(brow + r) * D_DIM + c4 * 4);
        }
        #pragma unroll
        for (int j = 0; j < 8; j++) {
            int i = tid + j * 256;
            int r = i >> 6, c4 = i & 63;
            cp16(Bs + r * BSTR + c4 * 4, Vt + (size_t)r * ER_DIM + c4 * 4);
        }
        if (tid < 64) {
            int r = tid >> 1, c4 = tid & 1;
            cp16(gws + r * 8 + c4 * 4, g_gwT + r * 8 + c4 * 4);
        }
        CP_COMMIT();
    }

    for (int c = 0; c < 32; c++) {
        const int buf = c & 1;
        if (c + 1 < 32) {
            const int k0 = (c + 1) * 32;
            const int nb = buf ^ 1;
            {
                int r = tid >> 3, c4 = tid & 7;
                cp16(xs + nb * 1152 + r * XSTR + c4 * 4,
                     xin + (size_t)(brow + r) * D_DIM + k0 + c4 * 4);
            }
            #pragma unroll
            for (int j = 0; j < 8; j++) {
                int i = tid + j * 256;
                int r = i >> 6, c4 = i & 63;
                cp16(Bs + nb * 8448 + r * BSTR + c4 * 4, Vt + (size_t)(k0 + r) * ER_DIM + c4 * 4);
            }
            if (tid < 64) {
                int r = tid >> 1, c4 = tid & 1;
                cp16(gws + nb * 256 + r * 8 + c4 * 4, g_gwT + (k0 + r) * 8 + c4 * 4);
            }
            CP_COMMIT();
            CP_WAIT1();
        } else {
            CP_WAIT0();
        }
        __syncthreads();

        const float* xb = xs + buf * 1152;
        const float* bb = Bs + buf * 8448;
        const float* gb = gws + buf * 256;
        const bool dogate = ((c & 7) == warp);
        #pragma unroll
        for (int kk = 0; kk < 4; kk++) {
            const int kb = kk * 8;
            uint32_t a[2][4];
            #pragma unroll
            for (int mt = 0; mt < 2; mt++) {
                const int r0 = mt * 16 + g;
                a[mt][0] = fu(rna_tf32(xb[r0 * XSTR + kb + t]));
                a[mt][1] = fu(rna_tf32(xb[(r0 + 8) * XSTR + kb + t]));
                a[mt][2] = fu(rna_tf32(xb[r0 * XSTR + kb + t + 4]));
                a[mt][3] = fu(rna_tf32(xb[(r0 + 8) * XSTR + kb + t + 4]));
            }
            #pragma unroll
            for (int nt = 0; nt < 4; nt++) {
                const int col = nbase + nt * 8 + g;
                uint32_t b0 = fu(bb[(kb + t) * BSTR + col]);
                uint32_t b1 = fu(bb[(kb + t + 4) * BSTR + col]);
                mma_tf32(acc + nt * 4,      a[0][0], a[0][1], a[0][2], a[0][3], b0, b1);
                mma_tf32(acc + 16 + nt * 4, a[1][0], a[1][1], a[1][2], a[1][3], b0, b1);
            }
            if (dogate) {   // reuse A fragments — only 2 extra LDS + 2 mma
                uint32_t gb0 = fu(gb[(kb + t) * 8 + g]);
                uint32_t gb1 = fu(gb[(kb + t + 4) * 8 + g]);
                mma_tf32(gacc,     a[0][0], a[0][1], a[0][2], a[0][3], gb0, gb1);
                mma_tf32(gacc + 4, a[1][0], a[1][1], a[1][2], a[1][3], gb0, gb1);
            }
        }
        __syncthreads();
    }

    // v1 = tanh(acc) -> vS (tf32-rounded);  gating partials -> gpart
    #pragma unroll
    for (int mt = 0; mt < 2; mt++) {
        const int r0 = mt * 16 + g;
        #pragma unroll
        for (int nt = 0; nt < 4; nt++) {
            const int col = nbase + nt * 8 + 2 * t;
            vS[r0 * VSTR + col]           = rna_tf32(tanhf(acc[mt * 16 + nt * 4 + 0]));
            vS[r0 * VSTR + col + 1]       = rna_tf32(tanhf(acc[mt * 16 + nt * 4 + 1]));
            vS[(r0 + 8) * VSTR + col]     = rna_tf32(tanhf(acc[mt * 16 + nt * 4 + 2]));
            vS[(r0 + 8) * VSTR + col + 1] = rna_tf32(tanhf(acc[mt * 16 + nt * 4 + 3]));
        }
        const int cc = 2 * t;
        gpart[warp * 256 + r0 * 8 + cc]           = gacc[mt * 4 + 0];
        gpart[warp * 256 + r0 * 8 + cc + 1]       = gacc[mt * 4 + 1];
        gpart[warp * 256 + (r0 + 8) * 8 + cc]     = gacc[mt * 4 + 2];
        gpart[warp * 256 + (r0 + 8) * 8 + cc + 1] = gacc[mt * 4 + 3];
    }
    __syncthreads();

    // softmax over experts (rows 0..31, e 0..3; 4-lane shfl groups)
    if (tid < 128) {
        const int row = tid >> 2, e = tid & 3;
        float s = 0.0f;
        #pragma unroll
        for (int w = 0; w < 8; w++) s += gpart[w * 256 + row * 8 + e];
        float m = s;
        m = fmaxf(m, __shfl_xor_sync(0xffffffffu, m, 1));
        m = fmaxf(m, __shfl_xor_sync(0xffffffffu, m, 2));
        float p = __expf(s - m);
        float su = p;
        su += __shfl_xor_sync(0xffffffffu, su, 1);
        su += __shfl_xor_sync(0xffffffffu, su, 2);
        gateS[tid] = p / su;
    }
    __syncthreads();

    // ============ Phase B: v2_pre = v1 @ Cb  (M=32, N=256, K=256) ============
    #pragma unroll
    for (int i = 0; i < 32; i++) acc[i] = 0.0f;

    {   // prologue
        #pragma unroll
        for (int j = 0; j < 8; j++) {
            int i = tid + j * 256;
            int r = i >> 6, c4 = i & 63;
            cp16(Bs + r * BSTR + c4 * 4, Cb + (size_t)r * ER_DIM + c4 * 4);
        }
        CP_COMMIT();
    }
    for (int c = 0; c < 8; c++) {
        const int buf = c & 1;
        if (c + 1 < 8) {
            const int k0 = (c + 1) * 32;
            const int nb = buf ^ 1;
            #pragma unroll
            for (int j = 0; j < 8; j++) {
                int i = tid + j * 256;
                int r = i >> 6, c4 = i & 63;
                cp16(Bs + nb * 8448 + r * BSTR + c4 * 4, Cb + (size_t)(k0 + r) * ER_DIM + c4 * 4);
            }
            CP_COMMIT();
            CP_WAIT1();
        } else {
            CP_WAIT0();
        }
        __syncthreads();

        const float* bb = Bs + buf * 8448;
        #pragma unroll
        for (int kk = 0; kk < 4; kk++) {
            const int kg = c * 32 + kk * 8;
            const int kb = kk * 8;
            uint32_t a[2][4];
            #pragma unroll
            for (int mt = 0; mt < 2; mt++) {
                const int r0 = mt * 16 + g;
                a[mt][0] = fu(vS[r0 * VSTR + kg + t]);
                a[mt][1] = fu(vS[(r0 + 8) * VSTR + kg + t]);
                a[mt][2] = fu(vS[r0 * VSTR + kg + t + 4]);
                a[mt][3] = fu(vS[(r0 + 8) * VSTR + kg + t + 4]);
            }
            #pragma unroll
            for (int nt = 0; nt < 4; nt++) {
                const int col = nbase + nt * 8 + g;
                uint32_t b0 = fu(bb[(kb + t) * BSTR + col]);
                uint32_t b1 = fu(bb[(kb + t + 4) * BSTR + col]);
                mma_tf32(acc + nt * 4,      a[0][0], a[0][1], a[0][2], a[0][3], b0, b1);
                mma_tf32(acc + 16 + nt * 4, a[1][0], a[1][1], a[1][2], a[1][3], b0, b1);
            }
        }
        __syncthreads();
    }

    // w = gate * tanh(v2_pre) -> overwrite vS (as wS), tf32-rounded
    #pragma unroll
    for (int mt = 0; mt < 2; mt++) {
        const int r0 = mt * 16 + g;
        #pragma unroll
        for (int nt = 0; nt < 4; nt++) {
            const int col = nbase + nt * 8 + 2 * t;   // even; col, col+1 same expert block
            const int e = col >> 6;
            const float g0 = gateS[r0 * 4 + e];
            const float g1 = gateS[(r0 + 8) * 4 + e];
            vS[r0 * VSTR + col]           = rna_tf32(g0 * tanhf(acc[mt * 16 + nt * 4 + 0]));
            vS[r0 * VSTR + col + 1]       = rna_tf32(g0 * tanhf(acc[mt * 16 + nt * 4 + 1]));
            vS[(r0 + 8) * VSTR + col]     = rna_tf32(g1 * tanhf(acc[mt * 16 + nt * 4 + 2]));
            vS[(r0 + 8) * VSTR + col + 1] = rna_tf32(g1 * tanhf(acc[mt * 16 + nt * 4 + 3]));
        }
    }
    __syncthreads();

    // ============ Phase C: out = w @ Ut (M=32, N=1024 in 4 chunks of 256, K=256) ============
    for (int nc = 0; nc < 4; nc++) {
        const int n0 = nc * 256;
        #pragma unroll
        for (int i = 0; i < 32; i++) acc[i] = 0.0f;

        {   // prologue
            #pragma unroll
            for (int j = 0; j < 8; j++) {
                int i = tid + j * 256;
                int r = i >> 6, c4 = i & 63;
                cp16(Bs + r * BSTR + c4 * 4, Ut + (size_t)r * D_DIM + n0 + c4 * 4);
            }
            CP_COMMIT();
        }
        for (int c = 0; c < 8; c++) {
            const int buf = c & 1;
            if (c + 1 < 8) {
                const int k0 = (c + 1) * 32;
                const int nb = buf ^ 1;
                #pragma unroll
                for (int j = 0; j < 8; j++) {
                    int i = tid + j * 256;
                    int r = i >> 6, c4 = i & 63;
                    cp16(Bs + nb * 8448 + r * BSTR + c4 * 4,
                         Ut + (size_t)(k0 + r) * D_DIM + n0 + c4 * 4);
                }
                CP_COMMIT();
                CP_WAIT1();
            } else {
                CP_WAIT0();
            }
            __syncthreads();

            const float* bb = Bs + buf * 8448;
            #pragma unroll
            for (int kk = 0; kk < 4; kk++) {
                const int kg = c * 32 + kk * 8;
                const int kb = kk * 8;
                uint32_t a[2][4];
                #pragma unroll
                for (int mt = 0; mt < 2; mt++) {
                    const int r0 = mt * 16 + g;
                    a[mt][0] = fu(vS[r0 * VSTR + kg + t]);
                    a[mt][1] = fu(vS[(r0 + 8) * VSTR + kg + t]);
                    a[mt][2] = fu(vS[r0 * VSTR + kg + t + 4]);
                    a[mt][3] = fu(vS[(r0 + 8) * VSTR + kg + t + 4]);
                }
                #pragma unroll
                for (int nt = 0; nt < 4; nt++) {
                    const int col = nbase + nt * 8 + g;
                    uint32_t b0 = fu(bb[(kb + t) * BSTR + col]);
                    uint32_t b1 = fu(bb[(kb + t + 4) * BSTR + col]);
                    mma_tf32(acc + nt * 4,      a[0][0], a[0][1], a[0][2], a[0][3], b0, b1);
                    mma_tf32(acc + 16 + nt * 4, a[1][0], a[1][1], a[1][2], a[1][3], b0, b1);
                }
            }
            __syncthreads();
        }

        // stage acc -> smem (Bs stage-0 region, free after final sync) for coalesced epilogue
        float* stg = Bs;
        #pragma unroll
        for (int mt = 0; mt < 2; mt++) {
            const int r0 = mt * 16 + g;
            #pragma unroll
            for (int nt = 0; nt < 4; nt++) {
                const int col = nbase + nt * 8 + 2 * t;
                stg[r0 * BSTR + col]           = acc[mt * 16 + nt * 4 + 0];
                stg[r0 * BSTR + col + 1]       = acc[mt * 16 + nt * 4 + 1];
                stg[(r0 + 8) * BSTR + col]     = acc[mt * 16 + nt * 4 + 2];
                stg[(r0 + 8) * BSTR + col + 1] = acc[mt * 16 + nt * 4 + 3];
            }
        }
        __syncthreads();

        // epilogue: out = x_l + x0 * (moe + bias)   (fully coalesced float4)
        #pragma unroll
        for (int j = 0; j < 8; j++) {
            int i = tid + j * 256;
            int r = i >> 6, c4 = i & 63;
            const int gr = brow + r;
            const int gc = n0 + c4 * 4;
            float4 s  = *reinterpret_cast<const float4*>(stg + r * BSTR + c4 * 4);
            float4 xv = *reinterpret_cast<const float4*>(xin + (size_t)gr * D_DIM + gc);
            float4 x0v = x0_is_xin ? xv
                       : *reinterpret_cast<const float4*>(x0g + (size_t)gr * D_DIM + gc);
            float4 bv = *reinterpret_cast<const float4*>(bl + gc);
            float4 o;
            o.x = xv.x + x0v.x * (s.x + bv.x);
            o.y = xv.y + x0v.y * (s.y + bv.y);
            o.z = xv.z + x0v.z * (s.z + bv.z);
            o.w = xv.w + x0v.w * (s.w + bv.w);
            *reinterpret_cast<float4*>(xout + (size_t)gr * D_DIM + gc) = o;
        }
        __syncthreads();
    }
}

// ---------------- launch ----------------
extern "C" void kernel_launch(void* const* d_in, const int* in_sizes, int n_in,
                              void* d_out, int out_size) {
    const float* inputs = (const float*)d_in[0];
    const float* U      = (const float*)d_in[1];
    const float* V      = (const float*)d_in[2];
    const float* C      = (const float*)d_in[3];
    const float* gw     = (const float*)d_in[4];
    const float* bias   = (const float*)d_in[5];
    float* out = (float*)d_out;
    (void)in_sizes; (void)n_in; (void)out_size;

    cudaFuncSetAttribute(layer_k, cudaFuncAttributeMaxDynamicSharedMemorySize, SMEM_BYTES);

    prep_k<<<1024, 256>>>(U, V, C, gw);
    layer_k<<<NBLK, NTHR, SMEM_BYTES>>>(inputs, out, inputs, bias, 0, 1);
    layer_k<<<NBLK, NTHR, SMEM_BYTES>>>(out,    out, inputs, bias, 1, 0);
    layer_k<<<NBLK, NTHR, SMEM_BYTES>>>(out,    out, inputs, bias, 2, 0);
}